// round 1
// baseline (speedup 1.0000x reference)
#include <cuda_runtime.h>
#include <math.h>

// ---------------- problem constants ----------------
#define BB   256
#define LL   64
#define DMOD 256
#define DI   512
#define DS   16
#define DC   4
#define DTRK 16
#define NLAY 4
#define TTOK (BB*LL)          // 16384 tokens
#define XDBL 48               // DTR + 2*DS

// ---------------- scratch (device globals, no allocation) ----------------
__device__ float g_feat[TTOK*DMOD];     // running features
__device__ float g_xz  [TTOK*2*DI];     // in_proj output (u | z)
__device__ float g_u   [TTOK*DI];       // conv+silu activated u
__device__ float g_xdbl[TTOK*XDBL];     // x_proj output
__device__ float g_gate[TTOK*DI];       // scan_out * silu(z)
__device__ float g_y2  [TTOK*DMOD];     // out_proj output (pre residual+LN)

// ---------------- helpers ----------------
__device__ __forceinline__ float blk_sum256(float v, float* sred) {
    int t = threadIdx.x;
    #pragma unroll
    for (int o = 16; o > 0; o >>= 1) v += __shfl_xor_sync(0xffffffffu, v, o);
    if ((t & 31) == 0) sred[t >> 5] = v;
    __syncthreads();
    if (t < 32) {
        float w = (t < 8) ? sred[t] : 0.f;
        #pragma unroll
        for (int o = 4; o > 0; o >>= 1) w += __shfl_xor_sync(0xffffffffu, w, o);
        if (t == 0) sred[8] = w;
    }
    __syncthreads();
    float r = sred[8];
    __syncthreads();
    return r;
}

__device__ __forceinline__ float silu_f(float x) {
    return x / (1.f + __expf(-x));
}
__device__ __forceinline__ float softplus_f(float x) {
    // stable: max(x,0) + log1p(exp(-|x|))   (== jax.nn.softplus)
    return fmaxf(x, 0.f) + log1pf(__expf(-fabsf(x)));
}

// ---------------- K0: embed + fusion + LN ----------------
// grid = BB blocks (one per batch), 256 threads. Dyn smem caches fusion_W.
__global__ void embed_fusion_ln(
    const float* __restrict__ x,
    const float* __restrict__ emb_proto, const float* __restrict__ emb_flags,
    const float* __restrict__ emb_dir,
    const float* __restrict__ plW, const float* __restrict__ plb,
    const float* __restrict__ piW, const float* __restrict__ pib,
    const float* __restrict__ fW, const float* __restrict__ fb,
    const float* __restrict__ lg, const float* __restrict__ lb,
    float* __restrict__ feat)
{
    extern __shared__ float sm[];
    float* sW   = sm;                 // 256*136
    float* scat = sm + DMOD*136;      // 136
    float* sred = scat + 136;         // 16
    int b = blockIdx.x, t = threadIdx.x;

    for (int i = t; i < DMOD*136; i += 256) sW[i] = fW[i];
    __syncthreads();

    for (int l = 0; l < LL; l++) {
        const float* xr = x + (size_t)(b*LL + l)*5;
        if (t < 136) {
            float v;
            if (t < 32)       { int p = min(max((int)xr[0], 0), 255); v = emb_proto[p*32 + t]; }
            else if (t < 64)  { v = xr[1]*plW[t-32] + plb[t-32]; }
            else if (t < 96)  { int f = min(max((int)xr[2], 0), 63); v = emb_flags[f*32 + (t-64)]; }
            else if (t < 128) { v = xr[3]*piW[t-96] + pib[t-96]; }
            else              { int d = min(max((int)xr[4], 0), 1); v = emb_dir[d*8 + (t-128)]; }
            scat[t] = v;
        }
        __syncthreads();

        float acc = fb[t];
        const float* wr = sW + t*136;
        #pragma unroll 8
        for (int j = 0; j < 136; j++) acc += wr[j]*scat[j];

        float m   = blk_sum256(acc, sred) * (1.f/DMOD);
        float d   = acc - m;
        float var = blk_sum256(d*d, sred) * (1.f/DMOD);
        feat[(size_t)(b*LL + l)*DMOD + t] = d * rsqrtf(var + 1e-5f) * lg[t] + lb[t];
        __syncthreads();
    }
}

// ---------------- generic GEMM: C[M,N] = A[M,K] * W[N,K]^T ----------------
#define GBM 128
#define GBN 64
#define GBK 16
__global__ __launch_bounds__(256)
void gemm_nt(const float* __restrict__ A, const float* __restrict__ W,
             float* __restrict__ C, int M, int N, int K)
{
    __shared__ float As[GBK][GBM];
    __shared__ float Bs[GBK][GBN];
    int tid  = threadIdx.x;
    int row0 = blockIdx.y * GBM;
    int col0 = blockIdx.x * GBN;

    int tn = tid & 15;   // 0..15 -> 4-wide col group
    int tm = tid >> 4;   // 0..15 -> 8-wide row group

    int lr = tid >> 2;          // 0..63
    int lk = (tid & 3) << 2;    // 0,4,8,12

    const float* Ap0 = A + (size_t)(row0 + lr)      * K + lk;
    const float* Ap1 = A + (size_t)(row0 + lr + 64) * K + lk;
    bool  bok = (col0 + lr) < N;
    const float* Wp  = W + (size_t)(bok ? (col0 + lr) : 0) * K + lk;

    float acc[8][4];
    #pragma unroll
    for (int i = 0; i < 8; i++)
        #pragma unroll
        for (int j = 0; j < 4; j++) acc[i][j] = 0.f;

    for (int k0 = 0; k0 < K; k0 += GBK) {
        float4 a0 = *(const float4*)(Ap0 + k0);
        float4 a1 = *(const float4*)(Ap1 + k0);
        float4 b0 = bok ? *(const float4*)(Wp + k0) : make_float4(0.f,0.f,0.f,0.f);

        As[lk+0][lr] = a0.x; As[lk+1][lr] = a0.y; As[lk+2][lr] = a0.z; As[lk+3][lr] = a0.w;
        As[lk+0][lr+64] = a1.x; As[lk+1][lr+64] = a1.y; As[lk+2][lr+64] = a1.z; As[lk+3][lr+64] = a1.w;
        Bs[lk+0][lr] = b0.x; Bs[lk+1][lr] = b0.y; Bs[lk+2][lr] = b0.z; Bs[lk+3][lr] = b0.w;
        __syncthreads();

        #pragma unroll
        for (int kk = 0; kk < GBK; kk++) {
            float4 t0 = *(const float4*)&As[kk][tm*8];
            float4 t1 = *(const float4*)&As[kk][tm*8 + 4];
            float4 t2 = *(const float4*)&Bs[kk][tn*4];
            float a[8] = {t0.x,t0.y,t0.z,t0.w,t1.x,t1.y,t1.z,t1.w};
            float bb[4] = {t2.x,t2.y,t2.z,t2.w};
            #pragma unroll
            for (int i = 0; i < 8; i++)
                #pragma unroll
                for (int j = 0; j < 4; j++)
                    acc[i][j] += a[i]*bb[j];
        }
        __syncthreads();
    }

    int c = col0 + tn*4;
    if (c < N) {
        #pragma unroll
        for (int i = 0; i < 8; i++) {
            int r = row0 + tm*8 + i;
            float4 v = make_float4(acc[i][0], acc[i][1], acc[i][2], acc[i][3]);
            *(float4*)(C + (size_t)r*N + c) = v;
        }
    }
}

// ---------------- depthwise causal conv (k=4) + bias + SiLU ----------------
// one thread per (b, d); grid 512 x 256
__global__ void conv_silu(const float* __restrict__ Wc, const float* __restrict__ bc)
{
    int idx = blockIdx.x * blockDim.x + threadIdx.x;
    int d = idx & (DI-1), b = idx >> 9;
    float w0 = Wc[d*DC+0], w1 = Wc[d*DC+1], w2 = Wc[d*DC+2], w3 = Wc[d*DC+3];
    float bias = bc[d];
    const float* src = g_xz + (size_t)b*LL*(2*DI) + d;
    float* dst = g_u + (size_t)b*LL*DI + d;
    float u0 = 0.f, u1 = 0.f, u2 = 0.f;
    for (int l = 0; l < LL; l++) {
        float u3 = src[(size_t)l*(2*DI)];
        float v  = u0*w0 + u1*w1 + u2*w2 + u3*w3 + bias;
        dst[(size_t)l*DI] = silu_f(v);
        u0 = u1; u1 = u2; u2 = u3;
    }
}

// ---------------- selective scan (dt_proj fused) ----------------
// one thread per (b, d)
__global__ void scan_kernel(const float* __restrict__ Wdt, const float* __restrict__ bdt,
                            const float* __restrict__ A_log, const float* __restrict__ Dp)
{
    int idx = blockIdx.x * blockDim.x + threadIdx.x;
    int d = idx & (DI-1), b = idx >> 9;

    float wdt[DS], A[DS], h[DS];
    #pragma unroll
    for (int n = 0; n < DS; n++) {
        wdt[n] = Wdt[d*DTRK + n];
        A[n]   = -__expf(A_log[d*DS + n]);
        h[n]   = 0.f;
    }
    float bdtd = bdt[d], Dd = Dp[d];

    const float* xd0 = g_xdbl + (size_t)b*LL*XDBL;
    const float* up  = g_u    + (size_t)b*LL*DI + d;
    const float* zp  = g_xz   + (size_t)b*LL*(2*DI) + DI + d;
    float* op        = g_gate + (size_t)b*LL*DI + d;

    for (int l = 0; l < LL; l++) {
        const float* xd = xd0 + (size_t)l*XDBL;
        float dtin = bdtd;
        #pragma unroll
        for (int n = 0; n < DTRK; n++) dtin += xd[n]*wdt[n];
        float dt = softplus_f(dtin);
        float ut = up[(size_t)l*DI];
        float du = dt*ut;
        float acc = 0.f;
        #pragma unroll
        for (int n = 0; n < DS; n++) {
            float Bn = xd[DTRK + n];
            float Cn = xd[DTRK + DS + n];
            h[n] = __expf(dt*A[n])*h[n] + du*Bn;
            acc += h[n]*Cn;
        }
        float y = acc + ut*Dd;
        float z = zp[(size_t)l*(2*DI)];
        op[(size_t)l*DI] = y * silu_f(z);
    }
}

// ---------------- residual add + LN (in place on feat) ----------------
__global__ void add_ln(const float* __restrict__ src, float* __restrict__ feat,
                       const float* __restrict__ lg, const float* __restrict__ lb)
{
    __shared__ float sred[16];
    int tok = blockIdx.x, t = threadIdx.x;
    float v = src[(size_t)tok*DMOD + t] + feat[(size_t)tok*DMOD + t];
    float m   = blk_sum256(v, sred) * (1.f/DMOD);
    float d   = v - m;
    float var = blk_sum256(d*d, sred) * (1.f/DMOD);
    feat[(size_t)tok*DMOD + t] = d * rsqrtf(var + 1e-5f) * lg[t] + lb[t];
}

// ---------------- early-exit classifiers ----------------
// grid = 3*BB blocks, 128 threads
__global__ void classify(const float* __restrict__ W1, const float* __restrict__ b1,
                         const float* __restrict__ W2, const float* __restrict__ b2,
                         float* __restrict__ out)
{
    __shared__ float hh[128];
    int e = blockIdx.x / BB;
    int b = blockIdx.x - e*BB;
    const int pos[3] = {7, 15, 31};
    const float* hvec = g_feat + (size_t)(b*LL + pos[e])*DMOD;
    int t = threadIdx.x;

    float acc = b1[e*128 + t];
    const float* w = W1 + (size_t)e*128*DMOD + (size_t)t*DMOD;
    #pragma unroll 8
    for (int j = 0; j < DMOD; j++) acc += w[j]*hvec[j];
    hh[t] = fmaxf(acc, 0.f);
    __syncthreads();

    if (t < 2) {
        float a = b2[e*2 + t];
        const float* w2 = W2 + (size_t)e*2*128 + (size_t)t*128;
        #pragma unroll 8
        for (int j = 0; j < 128; j++) a += w2[j]*hh[j];
        out[(size_t)e*BB*2 + b*2 + t] = a;
    }
}

// ---------------- launch ----------------
extern "C" void kernel_launch(void* const* d_in, const int* in_sizes, int n_in,
                              void* d_out, int out_size)
{
    const float* x          = (const float*)d_in[0];
    const float* emb_proto  = (const float*)d_in[1];
    const float* emb_flags  = (const float*)d_in[2];
    const float* emb_dir    = (const float*)d_in[3];
    const float* proj_len_W = (const float*)d_in[4];
    const float* proj_len_b = (const float*)d_in[5];
    const float* proj_iat_W = (const float*)d_in[6];
    const float* proj_iat_b = (const float*)d_in[7];
    const float* fusion_W   = (const float*)d_in[8];
    const float* fusion_b   = (const float*)d_in[9];
    const float* tok_ln_g   = (const float*)d_in[10];
    const float* tok_ln_b   = (const float*)d_in[11];
    const float* in_proj_W  = (const float*)d_in[12];
    const float* conv_W     = (const float*)d_in[13];
    const float* conv_b     = (const float*)d_in[14];
    const float* x_proj_W   = (const float*)d_in[15];
    const float* dt_proj_W  = (const float*)d_in[16];
    const float* dt_proj_b  = (const float*)d_in[17];
    const float* A_log      = (const float*)d_in[18];
    const float* Dvec       = (const float*)d_in[19];
    const float* out_proj_W = (const float*)d_in[20];
    const float* norm_g     = (const float*)d_in[21];
    const float* norm_b     = (const float*)d_in[22];
    const float* cls_W1     = (const float*)d_in[23];
    const float* cls_b1     = (const float*)d_in[24];
    const float* cls_W2     = (const float*)d_in[25];
    const float* cls_b2     = (const float*)d_in[26];
    float* out = (float*)d_out;

    float *p_feat, *p_xz, *p_u, *p_xdbl, *p_gate, *p_y2;
    cudaGetSymbolAddress((void**)&p_feat, g_feat);
    cudaGetSymbolAddress((void**)&p_xz,   g_xz);
    cudaGetSymbolAddress((void**)&p_u,    g_u);
    cudaGetSymbolAddress((void**)&p_xdbl, g_xdbl);
    cudaGetSymbolAddress((void**)&p_gate, g_gate);
    cudaGetSymbolAddress((void**)&p_y2,   g_y2);

    size_t embed_smem = (size_t)(DMOD*136 + 136 + 16) * sizeof(float);
    cudaFuncSetAttribute(embed_fusion_ln,
                         cudaFuncAttributeMaxDynamicSharedMemorySize, (int)embed_smem);

    embed_fusion_ln<<<BB, 256, embed_smem>>>(
        x, emb_proto, emb_flags, emb_dir,
        proj_len_W, proj_len_b, proj_iat_W, proj_iat_b,
        fusion_W, fusion_b, tok_ln_g, tok_ln_b, p_feat);

    for (int l = 0; l < NLAY; l++) {
        const float* Wi  = in_proj_W  + (size_t)l*2*DI*DMOD;
        const float* Wc  = conv_W     + (size_t)l*DI*DC;
        const float* bc  = conv_b     + (size_t)l*DI;
        const float* Wx  = x_proj_W   + (size_t)l*XDBL*DI;
        const float* Wdt = dt_proj_W  + (size_t)l*DI*DTRK;
        const float* bdt = dt_proj_b  + (size_t)l*DI;
        const float* Al  = A_log      + (size_t)l*DI*DS;
        const float* Dl  = Dvec       + (size_t)l*DI;
        const float* Wo  = out_proj_W + (size_t)l*DMOD*DI;

        // in_proj: xz = feat @ Wi^T   (M=16384, N=1024, K=256)
        gemm_nt<<<dim3(2*DI/GBN, TTOK/GBM), 256>>>(p_feat, Wi, p_xz, TTOK, 2*DI, DMOD);
        // conv + silu
        conv_silu<<<(BB*DI)/256, 256>>>(Wc, bc);
        // x_proj: xdbl = u @ Wx^T     (M=16384, N=48, K=512)
        gemm_nt<<<dim3((XDBL+GBN-1)/GBN, TTOK/GBM), 256>>>(p_u, Wx, p_xdbl, TTOK, XDBL, DI);
        // selective scan (dt_proj + gating fused)
        scan_kernel<<<(BB*DI)/256, 256>>>(Wdt, bdt, Al, Dl);
        // out_proj: y2 = gate @ Wo^T  (M=16384, N=256, K=512)
        gemm_nt<<<dim3(DMOD/GBN, TTOK/GBM), 256>>>(p_gate, Wo, p_y2, TTOK, DMOD, DI);
        // residual + LN
        add_ln<<<TTOK, 256>>>(p_y2, p_feat, norm_g, norm_b);
    }

    classify<<<3*BB, 128>>>(cls_W1, cls_b1, cls_W2, cls_b2, out);
}

// round 3
// speedup vs baseline: 1.4068x; 1.4068x over previous
#include <cuda_runtime.h>
#include <cstdint>
#include <math.h>

// ---------------- problem constants ----------------
#define BB   256
#define LL   64
#define DMOD 256
#define DI   512
#define DS   16
#define DC   4
#define DTRK 16
#define NLAY 4
#define TTOK (BB*LL)          // 16384 tokens
#define XDBL 48               // DTR + 2*DS (logical)
#define XPAD 64               // padded x_proj output stride

// ---------------- scratch (device globals, no allocation) ----------------
__device__ float g_feat [TTOK*DMOD];     // running features (fp32 exact)
__device__ float g_featr[TTOK*DMOD];     // tf32-rounded copy (GEMM A input)
__device__ float g_xz   [TTOK*2*DI];     // in_proj output (u | z)
__device__ float g_u    [TTOK*DI];       // conv+silu activated u (tf32-rounded)
__device__ float g_xdbl [TTOK*XPAD];     // x_proj output (padded to 64)
__device__ float g_gate [TTOK*DI];       // scan_out * silu(z) (tf32-rounded)
__device__ float g_y2   [TTOK*DMOD];     // out_proj output
// tf32-rounded weights
__device__ float g_Wir[NLAY*2*DI*DMOD];  // 4 x 1024 x 256
__device__ float g_Wxr[NLAY*XPAD*DI];    // 4 x 64 x 512 (rows 48..63 zero)
__device__ float g_Wor[NLAY*DMOD*DI];    // 4 x 256 x 512

// ---------------- small helpers ----------------
__device__ __forceinline__ float tf32r(float x) {
    uint32_t r; asm("cvt.rna.tf32.f32 %0, %1;" : "=r"(r) : "f"(x));
    return __uint_as_float(r);
}
__device__ __forceinline__ float silu_f(float x) { return x / (1.f + __expf(-x)); }
__device__ __forceinline__ float softplus_f(float x) {
    return fmaxf(x, 0.f) + log1pf(__expf(-fabsf(x)));
}
__device__ __forceinline__ float blk_sum256(float v, float* sred) {
    int t = threadIdx.x;
    #pragma unroll
    for (int o = 16; o > 0; o >>= 1) v += __shfl_xor_sync(0xffffffffu, v, o);
    if ((t & 31) == 0) sred[t >> 5] = v;
    __syncthreads();
    if (t < 32) {
        float w = (t < 8) ? sred[t] : 0.f;
        #pragma unroll
        for (int o = 4; o > 0; o >>= 1) w += __shfl_xor_sync(0xffffffffu, w, o);
        if (t == 0) sred[8] = w;
    }
    __syncthreads();
    float r = sred[8];
    __syncthreads();
    return r;
}

// ---------------- mma.sync tf32 (arch-generic tensor path) ----------------
__device__ __forceinline__ void mma_tf32(float* d, const uint32_t* a, const uint32_t* b) {
    asm volatile(
        "mma.sync.aligned.m16n8k8.row.col.f32.tf32.tf32.f32 "
        "{%0,%1,%2,%3}, {%4,%5,%6,%7}, {%8,%9}, {%0,%1,%2,%3};"
        : "+f"(d[0]), "+f"(d[1]), "+f"(d[2]), "+f"(d[3])
        : "r"(a[0]), "r"(a[1]), "r"(a[2]), "r"(a[3]), "r"(b[0]), "r"(b[1]));
}
__device__ __forceinline__ void cp16(uint32_t saddr, const void* gptr) {
    asm volatile("cp.async.ca.shared.global [%0], [%1], 16;" :: "r"(saddr), "l"(gptr) : "memory");
}

// ---------------- tensor GEMM: C[M,N] = A[M,K] * W[N,K]^T ----------------
// CTA tile 128 x BN, 8 warps (2m x 4n), warp tile 64 x BN/4, k-chunk 32,
// double-buffered smem (stride-36 rows: conflict-free LDS.32 frags + cp.async)
template<int BN>
__global__ __launch_bounds__(256)
void gemm_mma(const float* __restrict__ A, const float* __restrict__ W,
              float* __restrict__ C, int K, int N)
{
    extern __shared__ float sm[];
    constexpr int AST = 36;               // padded row stride (floats)
    constexpr int AFL = 128*AST;
    constexpr int BFL = BN*AST;
    constexpr int NT  = BN/32;            // n-tiles (of 8) per warp

    float* Asb[2] = { sm, sm + AFL };
    float* Bsb[2] = { sm + 2*AFL, sm + 2*AFL + BFL };

    const int tid = threadIdx.x;
    const int wid = tid >> 5, lid = tid & 31;
    const int g = lid >> 2, tig = lid & 3;
    const int mwarp = wid & 1;            // 0..1
    const int nwarp = wid >> 1;           // 0..3
    const int row0 = blockIdx.y*128, col0 = blockIdx.x*BN;

    float acc[4][NT][4];
    #pragma unroll
    for (int mt = 0; mt < 4; mt++)
        #pragma unroll
        for (int nt = 0; nt < NT; nt++)
            #pragma unroll
            for (int i = 0; i < 4; i++) acc[mt][nt][i] = 0.f;

    const int r_a = tid >> 3, kq_a = tid & 7;   // A: 4 float4/thread (rows r_a+32j)
    const float* Ag = A + (size_t)(row0 + r_a)*K + kq_a*4;
    const float* Bg = W + (size_t)(col0 + r_a)*K + kq_a*4;

    auto issue = [&](int c) {
        const int buf = c & 1;
        const int k0 = c << 5;
        float* As = Asb[buf];
        float* Bs = Bsb[buf];
        #pragma unroll
        for (int j = 0; j < 4; j++) {
            uint32_t sa = (uint32_t)__cvta_generic_to_shared(As + (r_a + 32*j)*AST + kq_a*4);
            cp16(sa, Ag + (size_t)(32*j)*K + k0);
        }
        #pragma unroll
        for (int j = 0; j < BN/32; j++) {
            uint32_t sa = (uint32_t)__cvta_generic_to_shared(Bs + (r_a + 32*j)*AST + kq_a*4);
            cp16(sa, Bg + (size_t)(32*j)*K + k0);
        }
        asm volatile("cp.async.commit_group;" ::: "memory");
    };

    const int NC = K >> 5;
    issue(0);
    for (int c = 0; c < NC; c++) {
        if (c + 1 < NC) {
            issue(c + 1);
            asm volatile("cp.async.wait_group 1;" ::: "memory");
        } else {
            asm volatile("cp.async.wait_group 0;" ::: "memory");
        }
        __syncthreads();

        const float* Ab = Asb[c & 1] + (mwarp*64 + g)*AST + tig;
        const float* Bb = Bsb[c & 1] + (nwarp*(BN/4) + g)*AST + tig;
        #pragma unroll
        for (int kt = 0; kt < 4; kt++) {
            uint32_t af[4][4], bf[NT][2];
            #pragma unroll
            for (int mt = 0; mt < 4; mt++) {
                af[mt][0] = __float_as_uint(Ab[(mt*16    )*AST + kt*8    ]);
                af[mt][1] = __float_as_uint(Ab[(mt*16 + 8)*AST + kt*8    ]);
                af[mt][2] = __float_as_uint(Ab[(mt*16    )*AST + kt*8 + 4]);
                af[mt][3] = __float_as_uint(Ab[(mt*16 + 8)*AST + kt*8 + 4]);
            }
            #pragma unroll
            for (int nt = 0; nt < NT; nt++) {
                bf[nt][0] = __float_as_uint(Bb[(nt*8)*AST + kt*8    ]);
                bf[nt][1] = __float_as_uint(Bb[(nt*8)*AST + kt*8 + 4]);
            }
            #pragma unroll
            for (int mt = 0; mt < 4; mt++)
                #pragma unroll
                for (int nt = 0; nt < NT; nt++)
                    mma_tf32(acc[mt][nt], af[mt], bf[nt]);
        }
        __syncthreads();
    }

    #pragma unroll
    for (int mt = 0; mt < 4; mt++) {
        const int row = row0 + mwarp*64 + mt*16 + g;
        #pragma unroll
        for (int nt = 0; nt < NT; nt++) {
            const int col = col0 + nwarp*(BN/4) + nt*8 + tig*2;
            *(float2*)&C[(size_t)row*N + col]       = make_float2(acc[mt][nt][0], acc[mt][nt][1]);
            *(float2*)&C[(size_t)(row + 8)*N + col] = make_float2(acc[mt][nt][2], acc[mt][nt][3]);
        }
    }
}

// ---------------- weight rounding (tf32 rna pre-round) ----------------
__global__ void round_weights(const float* __restrict__ Wi,
                              const float* __restrict__ Wx,
                              const float* __restrict__ Wo)
{
    int i = blockIdx.x * blockDim.x + threadIdx.x;
    if (i < NLAY*2*DI*DMOD) g_Wir[i] = tf32r(Wi[i]);
    if (i < NLAY*XPAD*DI) {
        int l = i >> 15;           // / (64*512)
        int r = (i >> 9) & 63;     // row within 64
        int k = i & 511;
        g_Wxr[i] = (r < XDBL) ? tf32r(Wx[((size_t)l*XDBL + r)*DI + k]) : 0.f;
    }
    if (i < NLAY*DMOD*DI) g_Wor[i] = tf32r(Wo[i]);
}

// ---------------- K0: embed + fusion + LN ----------------
__global__ void embed_fusion_ln(
    const float* __restrict__ x,
    const float* __restrict__ emb_proto, const float* __restrict__ emb_flags,
    const float* __restrict__ emb_dir,
    const float* __restrict__ plW, const float* __restrict__ plb,
    const float* __restrict__ piW, const float* __restrict__ pib,
    const float* __restrict__ fW, const float* __restrict__ fb,
    const float* __restrict__ lg, const float* __restrict__ lb,
    float* __restrict__ feat, float* __restrict__ featr)
{
    extern __shared__ float sm[];
    float* sW   = sm;                 // 256*136
    float* scat = sm + DMOD*136;      // 136
    float* sred = scat + 136;         // 16
    int b = blockIdx.x, t = threadIdx.x;

    for (int i = t; i < DMOD*136; i += 256) sW[i] = fW[i];
    __syncthreads();

    for (int l = 0; l < LL; l++) {
        const float* xr = x + (size_t)(b*LL + l)*5;
        if (t < 136) {
            float v;
            if (t < 32)       { int p = min(max((int)xr[0], 0), 255); v = emb_proto[p*32 + t]; }
            else if (t < 64)  { v = xr[1]*plW[t-32] + plb[t-32]; }
            else if (t < 96)  { int f = min(max((int)xr[2], 0), 63); v = emb_flags[f*32 + (t-64)]; }
            else if (t < 128) { v = xr[3]*piW[t-96] + pib[t-96]; }
            else              { int d = min(max((int)xr[4], 0), 1); v = emb_dir[d*8 + (t-128)]; }
            scat[t] = v;
        }
        __syncthreads();

        float acc = fb[t];
        const float* wr = sW + t*136;
        #pragma unroll 8
        for (int j = 0; j < 136; j++) acc += wr[j]*scat[j];

        float m   = blk_sum256(acc, sred) * (1.f/DMOD);
        float d   = acc - m;
        float var = blk_sum256(d*d, sred) * (1.f/DMOD);
        float out = d * rsqrtf(var + 1e-5f) * lg[t] + lb[t];
        feat [(size_t)(b*LL + l)*DMOD + t] = out;
        featr[(size_t)(b*LL + l)*DMOD + t] = tf32r(out);
        __syncthreads();
    }
}

// ---------------- depthwise causal conv (k=4) + bias + SiLU ----------------
__global__ void conv_silu(const float* __restrict__ Wc, const float* __restrict__ bc)
{
    int idx = blockIdx.x * blockDim.x + threadIdx.x;
    int d = idx & (DI-1), b = idx >> 9;
    float w0 = Wc[d*DC+0], w1 = Wc[d*DC+1], w2 = Wc[d*DC+2], w3 = Wc[d*DC+3];
    float bias = bc[d];
    const float* src = g_xz + (size_t)b*LL*(2*DI) + d;
    float* dst = g_u + (size_t)b*LL*DI + d;
    float u0 = 0.f, u1 = 0.f, u2 = 0.f;
    for (int l = 0; l < LL; l++) {
        float u3 = src[(size_t)l*(2*DI)];
        float v  = u0*w0 + u1*w1 + u2*w2 + u3*w3 + bias;
        dst[(size_t)l*DI] = tf32r(silu_f(v));
        u0 = u1; u1 = u2; u2 = u3;
    }
}

// ---------------- selective scan (dt_proj fused) ----------------
__global__ void scan_kernel(const float* __restrict__ Wdt, const float* __restrict__ bdt,
                            const float* __restrict__ A_log, const float* __restrict__ Dp)
{
    int idx = blockIdx.x * blockDim.x + threadIdx.x;
    int d = idx & (DI-1), b = idx >> 9;

    float wdt[DS], A[DS], h[DS];
    #pragma unroll
    for (int n = 0; n < DS; n++) {
        wdt[n] = Wdt[d*DTRK + n];
        A[n]   = -__expf(A_log[d*DS + n]);
        h[n]   = 0.f;
    }
    float bdtd = bdt[d], Dd = Dp[d];

    const float* xd0 = g_xdbl + (size_t)b*LL*XPAD;
    const float* up  = g_u    + (size_t)b*LL*DI + d;
    const float* zp  = g_xz   + (size_t)b*LL*(2*DI) + DI + d;
    float* op        = g_gate + (size_t)b*LL*DI + d;

    for (int l = 0; l < LL; l++) {
        const float* xd = xd0 + (size_t)l*XPAD;
        float dtin = bdtd;
        #pragma unroll
        for (int n = 0; n < DTRK; n++) dtin += xd[n]*wdt[n];
        float dt = softplus_f(dtin);
        float ut = up[(size_t)l*DI];
        float du = dt*ut;
        float acc = 0.f;
        #pragma unroll
        for (int n = 0; n < DS; n++) {
            float Bn = xd[DTRK + n];
            float Cn = xd[DTRK + DS + n];
            h[n] = __expf(dt*A[n])*h[n] + du*Bn;
            acc += h[n]*Cn;
        }
        float y = acc + ut*Dd;
        float z = zp[(size_t)l*(2*DI)];
        op[(size_t)l*DI] = tf32r(y * silu_f(z));
    }
}

// ---------------- residual add + LN ----------------
__global__ void add_ln(const float* __restrict__ src, float* __restrict__ feat,
                       float* __restrict__ featr,
                       const float* __restrict__ lg, const float* __restrict__ lb)
{
    __shared__ float sred[16];
    int tok = blockIdx.x, t = threadIdx.x;
    float v = src[(size_t)tok*DMOD + t] + feat[(size_t)tok*DMOD + t];
    float m   = blk_sum256(v, sred) * (1.f/DMOD);
    float d   = v - m;
    float var = blk_sum256(d*d, sred) * (1.f/DMOD);
    float out = d * rsqrtf(var + 1e-5f) * lg[t] + lb[t];
    feat [(size_t)tok*DMOD + t] = out;
    featr[(size_t)tok*DMOD + t] = tf32r(out);
}

// ---------------- early-exit classifiers ----------------
__global__ void classify(const float* __restrict__ W1, const float* __restrict__ b1,
                         const float* __restrict__ W2, const float* __restrict__ b2,
                         float* __restrict__ out)
{
    __shared__ float hh[128];
    int e = blockIdx.x / BB;
    int b = blockIdx.x - e*BB;
    const int pos[3] = {7, 15, 31};
    const float* hvec = g_feat + (size_t)(b*LL + pos[e])*DMOD;
    int t = threadIdx.x;

    float acc = b1[e*128 + t];
    const float* w = W1 + (size_t)e*128*DMOD + (size_t)t*DMOD;
    #pragma unroll 8
    for (int j = 0; j < DMOD; j++) acc += w[j]*hvec[j];
    hh[t] = fmaxf(acc, 0.f);
    __syncthreads();

    if (t < 2) {
        float a = b2[e*2 + t];
        const float* w2 = W2 + (size_t)e*2*128 + (size_t)t*128;
        #pragma unroll 8
        for (int j = 0; j < 128; j++) a += w2[j]*hh[j];
        out[(size_t)e*BB*2 + b*2 + t] = a;
    }
}

// ---------------- launch ----------------
extern "C" void kernel_launch(void* const* d_in, const int* in_sizes, int n_in,
                              void* d_out, int out_size)
{
    const float* x          = (const float*)d_in[0];
    const float* emb_proto  = (const float*)d_in[1];
    const float* emb_flags  = (const float*)d_in[2];
    const float* emb_dir    = (const float*)d_in[3];
    const float* proj_len_W = (const float*)d_in[4];
    const float* proj_len_b = (const float*)d_in[5];
    const float* proj_iat_W = (const float*)d_in[6];
    const float* proj_iat_b = (const float*)d_in[7];
    const float* fusion_W   = (const float*)d_in[8];
    const float* fusion_b   = (const float*)d_in[9];
    const float* tok_ln_g   = (const float*)d_in[10];
    const float* tok_ln_b   = (const float*)d_in[11];
    const float* in_proj_W  = (const float*)d_in[12];
    const float* conv_W     = (const float*)d_in[13];
    const float* conv_b     = (const float*)d_in[14];
    const float* x_proj_W   = (const float*)d_in[15];
    const float* dt_proj_W  = (const float*)d_in[16];
    const float* dt_proj_b  = (const float*)d_in[17];
    const float* A_log      = (const float*)d_in[18];
    const float* Dvec       = (const float*)d_in[19];
    const float* out_proj_W = (const float*)d_in[20];
    const float* norm_g     = (const float*)d_in[21];
    const float* norm_b     = (const float*)d_in[22];
    const float* cls_W1     = (const float*)d_in[23];
    const float* cls_b1     = (const float*)d_in[24];
    const float* cls_W2     = (const float*)d_in[25];
    const float* cls_b2     = (const float*)d_in[26];
    float* out = (float*)d_out;

    float *p_feat, *p_featr, *p_xz, *p_u, *p_xdbl, *p_gate, *p_y2;
    float *p_Wir, *p_Wxr, *p_Wor;
    cudaGetSymbolAddress((void**)&p_feat,  g_feat);
    cudaGetSymbolAddress((void**)&p_featr, g_featr);
    cudaGetSymbolAddress((void**)&p_xz,    g_xz);
    cudaGetSymbolAddress((void**)&p_u,     g_u);
    cudaGetSymbolAddress((void**)&p_xdbl,  g_xdbl);
    cudaGetSymbolAddress((void**)&p_gate,  g_gate);
    cudaGetSymbolAddress((void**)&p_y2,    g_y2);
    cudaGetSymbolAddress((void**)&p_Wir,   g_Wir);
    cudaGetSymbolAddress((void**)&p_Wxr,   g_Wxr);
    cudaGetSymbolAddress((void**)&p_Wor,   g_Wor);

    size_t embed_smem = (size_t)(DMOD*136 + 136 + 16) * sizeof(float);
    cudaFuncSetAttribute(embed_fusion_ln,
                         cudaFuncAttributeMaxDynamicSharedMemorySize, (int)embed_smem);
    const int SME128 = 2*(128*36 + 128*36)*4;   // 73728
    const int SME64  = 2*(128*36 +  64*36)*4;   // 55296
    cudaFuncSetAttribute(gemm_mma<128>, cudaFuncAttributeMaxDynamicSharedMemorySize, SME128);
    cudaFuncSetAttribute(gemm_mma<64>,  cudaFuncAttributeMaxDynamicSharedMemorySize, SME64);

    round_weights<<<(NLAY*2*DI*DMOD + 255)/256, 256>>>(in_proj_W, x_proj_W, out_proj_W);

    embed_fusion_ln<<<BB, 256, embed_smem>>>(
        x, emb_proto, emb_flags, emb_dir,
        proj_len_W, proj_len_b, proj_iat_W, proj_iat_b,
        fusion_W, fusion_b, tok_ln_g, tok_ln_b, p_feat, p_featr);

    for (int l = 0; l < NLAY; l++) {
        const float* Wc  = conv_W     + (size_t)l*DI*DC;
        const float* bc  = conv_b     + (size_t)l*DI;
        const float* Wdt = dt_proj_W  + (size_t)l*DI*DTRK;
        const float* bdt = dt_proj_b  + (size_t)l*DI;
        const float* Al  = A_log      + (size_t)l*DI*DS;
        const float* Dl  = Dvec       + (size_t)l*DI;

        // in_proj: xz = featr @ Wir^T   (M=16384, N=1024, K=256)
        gemm_mma<128><<<dim3(2*DI/128, TTOK/128), 256, SME128>>>(
            p_featr, p_Wir + (size_t)l*2*DI*DMOD, p_xz, DMOD, 2*DI);
        // conv + silu (writes tf32-rounded u)
        conv_silu<<<(BB*DI)/256, 256>>>(Wc, bc);
        // x_proj: xdbl = u @ Wxr^T      (M=16384, N=64(pad), K=512)
        gemm_mma<64><<<dim3(1, TTOK/128), 256, SME64>>>(
            p_u, p_Wxr + (size_t)l*XPAD*DI, p_xdbl, DI, XPAD);
        // selective scan (writes tf32-rounded gate)
        scan_kernel<<<(BB*DI)/256, 256>>>(Wdt, bdt, Al, Dl);
        // out_proj: y2 = gate @ Wor^T   (M=16384, N=256, K=512)
        gemm_mma<128><<<dim3(DMOD/128, TTOK/128), 256, SME128>>>(
            p_gate, p_Wor + (size_t)l*DMOD*DI, p_y2, DI, DMOD);
        // residual + LN
        add_ln<<<TTOK, 256>>>(p_y2, p_feat, p_featr, norm_g, norm_b);
    }

    classify<<<3*BB, 128>>>(cls_W1, cls_b1, cls_W2, cls_b2, out);
}